// round 3
// baseline (speedup 1.0000x reference)
#include <cuda_runtime.h>
#include <math.h>

#define BB 4
#define CC 32
#define HH 512
#define WW 512
#define PP (HH*WW)          // 262144
#define NI 8
#define EE 512
#define NPTS (NI*EE)        // 4096
#define NPAIRS 28

// ---------------- device scratch (static globals; no allocations) -------------
__device__ float g_sums[BB][NI][CC];
__device__ float g_counts[BB][NI];
__device__ float g_means[BB][NI][CC];
__device__ float g_hinge[BB][NI];
__device__ int   g_sel[BB][NI][EE];
__device__ float g_eb[BB][CC][NPTS];   // channel-major gathered edge features
__device__ float g_sq[BB][NPTS];       // squared norms of edge features
__device__ float g_dist_raw;
__device__ float g_edge_raw;
__device__ float g_reg_raw;

// ---------------------------------------------------------------- zero scratch
__global__ void k_zero() {
    int i = blockIdx.x * blockDim.x + threadIdx.x;
    int stride = gridDim.x * blockDim.x;
    float* sums = &g_sums[0][0][0];
    for (int k = i; k < BB*NI*CC; k += stride) sums[k] = 0.0f;
    if (i < BB*NI) {
        (&g_counts[0][0])[i] = 0.0f;
        (&g_hinge[0][0])[i]  = 0.0f;
    }
    int* sel = &g_sel[0][0][0];
    for (int k = i; k < BB*NI*EE; k += stride) sel[k] = 0;
    if (i == 0) { g_dist_raw = 0.0f; g_edge_raw = 0.0f; g_reg_raw = 0.0f; }
}

// ------------------------------------------------- pass A: label sums + counts
// grid = BB * NCHUNK_S blocks, 256 threads (8 warps). Warp w owns channels
// [4w, 4w+4); every warp sweeps the whole pixel chunk so accumulators stay in
// registers (acc[8 labels][4 channels]) and we reduce once at the end.
#define NCHUNK_S 128
#define CHPX_S (PP / NCHUNK_S)   // 2048

__global__ __launch_bounds__(256) void k_stats(const float* __restrict__ feat,
                                               const int* __restrict__ labels) {
    int b = blockIdx.x / NCHUNK_S;
    int chunk = blockIdx.x % NCHUNK_S;
    int base = chunk * CHPX_S;
    const float* f = feat + (size_t)b * CC * PP;
    const int* lb = labels + (size_t)b * PP;

    int t = threadIdx.x;
    int w = t >> 5, lane = t & 31;
    int c0 = w * 4;

    float acc[NI][4];
#pragma unroll
    for (int n = 0; n < NI; n++)
#pragma unroll
        for (int e = 0; e < 4; e++) acc[n][e] = 0.0f;
    int cnt[NI];
#pragma unroll
    for (int n = 0; n < NI; n++) cnt[n] = 0;

    for (int it = 0; it < CHPX_S / 32; it++) {
        int p = base + it * 32 + lane;
        int l = lb[p];
        float v0 = f[(size_t)(c0 + 0) * PP + p];
        float v1 = f[(size_t)(c0 + 1) * PP + p];
        float v2 = f[(size_t)(c0 + 2) * PP + p];
        float v3 = f[(size_t)(c0 + 3) * PP + p];
#pragma unroll
        for (int n = 0; n < NI; n++) {
            bool m = (l == n);
            acc[n][0] += m ? v0 : 0.0f;
            acc[n][1] += m ? v1 : 0.0f;
            acc[n][2] += m ? v2 : 0.0f;
            acc[n][3] += m ? v3 : 0.0f;
        }
        if (w == 0) {
#pragma unroll
            for (int n = 0; n < NI; n++) cnt[n] += (l == n) ? 1 : 0;
        }
    }

    // warp butterfly reduce all 32 accumulators, lane 0 commits to global
#pragma unroll
    for (int n = 0; n < NI; n++)
#pragma unroll
        for (int e = 0; e < 4; e++) {
            float a = acc[n][e];
#pragma unroll
            for (int o = 16; o > 0; o >>= 1) a += __shfl_xor_sync(0xffffffffu, a, o);
            acc[n][e] = a;
        }
    if (lane == 0) {
#pragma unroll
        for (int n = 0; n < NI; n++)
#pragma unroll
            for (int e = 0; e < 4; e++)
                atomicAdd(&g_sums[b][n][c0 + e], acc[n][e]);
    }
    if (w == 0) {
#pragma unroll
        for (int n = 0; n < NI; n++) {
            int a = cnt[n];
#pragma unroll
            for (int o = 16; o > 0; o >>= 1) a += __shfl_xor_sync(0xffffffffu, a, o);
            cnt[n] = a;
        }
        if (lane == 0) {
#pragma unroll
            for (int n = 0; n < NI; n++)
                atomicAdd(&g_counts[b][n], (float)cnt[n]);
        }
    }
}

// ----------------------------------- means + dist loss + reg loss (tiny work)
__global__ void k_means() {
    int b = blockIdx.x;
    int t = threadIdx.x;          // 256
    int n = t >> 5, c = t & 31;   // warp == instance
    float cntv = g_counts[b][n];
    float mean = g_sums[b][n][c] / cntv;
    g_means[b][n][c] = mean;
    __shared__ float sm[NI][CC];
    __shared__ float sM2[NI];
    sm[n][c] = mean;
    float m2 = mean * mean;
#pragma unroll
    for (int o = 16; o > 0; o >>= 1) m2 += __shfl_xor_sync(0xffffffffu, m2, o);
    if (c == 0) sM2[n] = m2;
    __syncthreads();
    if (t == 0) {
        float r = 0.0f;
#pragma unroll
        for (int nn = 0; nn < NI; nn++)
            r += sqrtf(fmaxf(sM2[nn], 0.0f) + 1e-12f);
        atomicAdd(&g_reg_raw, r * (1.0f / (float)NI));
    }
    if (t < NPAIRS) {
        int i = 0, rem = t;
        while (rem >= (NI - 1) - i) { rem -= (NI - 1) - i; i++; }
        int j = i + 1 + rem;
        float d2 = 0.0f;
#pragma unroll
        for (int cc2 = 0; cc2 < CC; cc2++) {
            float df = sm[i][cc2] - sm[j][cc2];
            d2 += df * df;
        }
        float dm = sqrtf(fmaxf(d2, 0.0f) + 1e-12f);
        float h = fmaxf(3.0f - dm, 0.0f);   // 2*DD - dm
        atomicAdd(&g_dist_raw, h * h);
    }
}

// ------------------------------------------------ pass B: variance (pull) loss
// grid = BB * NCHUNK_V, 256 threads; each thread owns 16 pixels (4 groups of 4
// consecutive pixels -> float4 loads). Mean table in padded shared (stride 36
// floats -> no 8-way bank conflict, float4 loads stay 16B aligned).
#define NCHUNK_V 64
#define CHPX_V (PP / NCHUNK_V)   // 4096

__global__ __launch_bounds__(256) void k_var(const float* __restrict__ feat,
                                             const int* __restrict__ labels) {
    int b = blockIdx.x / NCHUNK_V;
    int chunk = blockIdx.x % NCHUNK_V;
    int base = chunk * CHPX_V;
    const float* f = feat + (size_t)b * CC * PP;
    const int* lb = labels + (size_t)b * PP;
    int t = threadIdx.x;

    __shared__ float sm[NI * 36];
    { int n = t >> 5, c = t & 31; sm[n * 36 + c] = g_means[b][n][c]; }
    __syncthreads();

    int labv[16];
#pragma unroll
    for (int k = 0; k < 4; k++) {
        int4 L = *(const int4*)&lb[base + (t + k * 256) * 4];
        labv[k * 4 + 0] = L.x; labv[k * 4 + 1] = L.y;
        labv[k * 4 + 2] = L.z; labv[k * 4 + 3] = L.w;
    }

    float d2[16];
#pragma unroll
    for (int q = 0; q < 16; q++) d2[q] = 0.0f;

#pragma unroll
    for (int k = 0; k < 4; k++) {
        int pbase = base + (t + k * 256) * 4;
#pragma unroll
        for (int cg = 0; cg < 8; cg++) {
            float vv[4][4];
#pragma unroll
            for (int e = 0; e < 4; e++) {
                float4 v = *(const float4*)&f[(size_t)(cg * 4 + e) * PP + pbase];
                vv[e][0] = v.x; vv[e][1] = v.y; vv[e][2] = v.z; vv[e][3] = v.w;
            }
#pragma unroll
            for (int j = 0; j < 4; j++) {
                float4 m = *(const float4*)&sm[labv[k * 4 + j] * 36 + cg * 4];
                float t0 = vv[0][j] - m.x;
                float t1 = vv[1][j] - m.y;
                float t2 = vv[2][j] - m.z;
                float t3 = vv[3][j] - m.w;
                d2[k * 4 + j] += t0 * t0 + t1 * t1 + t2 * t2 + t3 * t3;
            }
        }
    }

    float hacc[NI];
#pragma unroll
    for (int n = 0; n < NI; n++) hacc[n] = 0.0f;
#pragma unroll
    for (int q = 0; q < 16; q++) {
        float d = sqrtf(d2[q] + 1e-12f);          // d2 >= 0 exactly
        float h = fmaxf(d - 0.5f, 0.0f);          // DV = 0.5
        float hs = h * h;
        int l = labv[q];
#pragma unroll
        for (int n = 0; n < NI; n++) hacc[n] += (l == n) ? hs : 0.0f;
    }
#pragma unroll
    for (int n = 0; n < NI; n++) {
        float a = hacc[n];
#pragma unroll
        for (int o = 16; o > 0; o >>= 1) a += __shfl_xor_sync(0xffffffffu, a, o);
        hacc[n] = a;
    }
    if ((t & 31) == 0) {
#pragma unroll
        for (int n = 0; n < NI; n++) atomicAdd(&g_hinge[b][n], hacc[n]);
    }
}

// ------------------------- edge selection: first EE pixels (ascending index)
// One block per (b, instance): per-thread contiguous chunks keep pixel order,
// block prefix scan gives the global rank, second pass writes ranks < EE.
__global__ __launch_bounds__(1024) void k_select(const int* __restrict__ labelEdges) {
    int b = blockIdx.x >> 3;
    int inst = blockIdx.x & 7;
    const int* le = labelEdges + (size_t)b * PP;
    int t = threadIdx.x;                 // 1024 threads
    const int PT = PP / 1024;            // 256 pixels per thread
    int start = t * PT;

    int cnt = 0;
    for (int k = 0; k < PT / 4; k++) {
        int4 q = *(const int4*)&le[start + k * 4];
        cnt += (q.x == inst) + (q.y == inst) + (q.z == inst) + (q.w == inst);
    }
    __shared__ int s[1024];
    s[t] = cnt;
    __syncthreads();
    for (int off = 1; off < 1024; off <<= 1) {
        int v = (t >= off) ? s[t - off] : 0;
        __syncthreads();
        if (t >= off) s[t] += v;
        __syncthreads();
    }
    int rank = s[t] - cnt;   // exclusive prefix
    if (rank < EE && cnt > 0) {
        for (int k = 0; k < PT / 4; k++) {
            int4 q = *(const int4*)&le[start + k * 4];
            int p = start + k * 4;
            if (q.x == inst) { if (rank < EE) g_sel[b][inst][rank] = p;     rank++; }
            if (q.y == inst) { if (rank < EE) g_sel[b][inst][rank] = p + 1; rank++; }
            if (q.z == inst) { if (rank < EE) g_sel[b][inst][rank] = p + 2; rank++; }
            if (q.w == inst) { if (rank < EE) g_sel[b][inst][rank] = p + 3; rank++; }
            if (rank >= EE) break;
        }
    }
}

// ------------------------------------ gather edge features + squared norms
__global__ __launch_bounds__(256) void k_gather(const float* __restrict__ feat) {
    int b = blockIdx.x >> 4;
    int blk = blockIdx.x & 15;
    int pt = blk * 256 + threadIdx.x;    // 0..4095
    int inst = pt >> 9;
    int r = pt & (EE - 1);
    int idx = g_sel[b][inst][r];
    const float* f = feat + (size_t)b * CC * PP;
    float sq = 0.0f;
#pragma unroll
    for (int c = 0; c < CC; c++) {
        float v = f[(size_t)c * PP + idx];
        g_eb[b][c][pt] = v;
        sq += v * v;
    }
    g_sq[b][pt] = sq;
}

// ----------------------- edge pair loss: 64x64 register-blocked "GEMM" tiles
// grid = (28 pairs * 64 tiles, BB). 256 threads, 4x4 micro-tile per thread.
__global__ __launch_bounds__(256) void k_pairs() {
    int b = blockIdx.y;
    int id = blockIdx.x;
    int pair = id >> 6;
    int tile = id & 63;
    int i = 0, rem = pair;
    while (rem >= (NI - 1) - i) { rem -= (NI - 1) - i; i++; }
    int j = i + 1 + rem;
    int ti = tile >> 3, tj = tile & 7;
    int i0 = i * EE + ti * 64;
    int j0 = j * EE + tj * 64;

    __shared__ float As[CC][64];
    __shared__ float Bs[CC][64];
    __shared__ float sqA[64], sqB[64];
    __shared__ float swarp[8];

    int t = threadIdx.x;
#pragma unroll
    for (int r2 = 0; r2 < 2; r2++) {
        int l = t + r2 * 256;        // 0..511 float4 slots
        int c = l >> 4, k4 = l & 15;
        *(float4*)&As[c][k4 * 4] = *(const float4*)&g_eb[b][c][i0 + k4 * 4];
        *(float4*)&Bs[c][k4 * 4] = *(const float4*)&g_eb[b][c][j0 + k4 * 4];
    }
    if (t < 64) sqA[t] = g_sq[b][i0 + t];
    else if (t < 128) sqB[t - 64] = g_sq[b][j0 + (t - 64)];
    __syncthreads();

    int ty = t >> 4, tx = t & 15;
    float dot[4][4];
#pragma unroll
    for (int a = 0; a < 4; a++)
#pragma unroll
        for (int bb2 = 0; bb2 < 4; bb2++) dot[a][bb2] = 0.0f;

#pragma unroll
    for (int c = 0; c < CC; c++) {
        float4 av = *(const float4*)&As[c][ty * 4];
        float4 bv = *(const float4*)&Bs[c][tx * 4];
        float a[4] = {av.x, av.y, av.z, av.w};
        float bvv[4] = {bv.x, bv.y, bv.z, bv.w};
#pragma unroll
        for (int ii = 0; ii < 4; ii++)
#pragma unroll
            for (int jj = 0; jj < 4; jj++)
                dot[ii][jj] += a[ii] * bvv[jj];
    }

    float acc = 0.0f;
#pragma unroll
    for (int ii = 0; ii < 4; ii++) {
        float sa = sqA[ty * 4 + ii];
#pragma unroll
        for (int jj = 0; jj < 4; jj++) {
            float d2 = sa + sqB[tx * 4 + jj] - 2.0f * dot[ii][jj];
            if (d2 < 4.0f) {   // only then can relu(2 - pd) be positive
                float pd = sqrtf(fmaxf(d2, 0.0f) + 1e-12f);
                float h = fmaxf(2.0f - pd, 0.0f);   // 2*(DD-DV) = 2
                acc += h * h;
            }
        }
    }
#pragma unroll
    for (int o = 16; o > 0; o >>= 1) acc += __shfl_xor_sync(0xffffffffu, acc, o);
    if ((t & 31) == 0) swarp[t >> 5] = acc;
    __syncthreads();
    if (t == 0) {
        float s2 = 0.0f;
#pragma unroll
        for (int w = 0; w < 8; w++) s2 += swarp[w];
        if (s2 != 0.0f) atomicAdd(&g_edge_raw, s2);
    }
}

// --------------------------------------------------------------- finalize
__global__ void k_final(float* __restrict__ out) {
    int t = threadIdx.x;   // 32 threads: (b,n) pairs
    float v = g_hinge[t >> 3][t & 7] / g_counts[t >> 3][t & 7];
#pragma unroll
    for (int o = 16; o > 0; o >>= 1) v += __shfl_xor_sync(0xffffffffu, v, o);
    if (t == 0) {
        float var  = v * (1.0f / (float)NI);                       // ALPHA = 1
        float dist = g_dist_raw * (1.0f / 56.0f);                  // BETA = 1
        float edge = g_edge_raw * (1.0f / (512.0f * 512.0f * 56.0f)); // GAMMA = 1
        float reg  = 0.001f * g_reg_raw;                           // DELTA
        out[0] = var + dist + edge + reg;
        out[1] = var;
        out[2] = dist;
        out[3] = edge;
        out[4] = reg;
    }
}

// ------------------------------------------------------------------ launcher
extern "C" void kernel_launch(void* const* d_in, const int* in_sizes, int n_in,
                              void* d_out, int out_size) {
    const float* features   = (const float*)d_in[0];
    const int*   labels     = (const int*)d_in[1];
    const int*   labelEdges = (const int*)d_in[2];
    float* out = (float*)d_out;
    (void)in_sizes; (void)n_in; (void)out_size;

    k_zero<<<16, 256>>>();
    k_stats<<<BB * NCHUNK_S, 256>>>(features, labels);
    k_means<<<BB, 256>>>();
    k_var<<<BB * NCHUNK_V, 256>>>(features, labels);
    k_select<<<BB * NI, 1024>>>(labelEdges);
    k_gather<<<BB * 16, 256>>>(features);
    k_pairs<<<dim3(NPAIRS * 64, BB), 256>>>();
    k_final<<<1, 32>>>(out);
}

// round 4
// speedup vs baseline: 1.3051x; 1.3051x over previous
#include <cuda_runtime.h>
#include <cuda_bf16.h>
#include <math.h>

#define BB 4
#define CC 32
#define PP 262144
#define NI 8
#define EE 512
#define NPTS 4096
#define NPAIRS 28

// ---------------- device scratch (static globals; no allocations) -------------
__device__ float g_sums[BB][NI][CC];
__device__ float g_counts[BB][NI];
__device__ float g_means[BB][NI][CC];
__device__ float g_invc[BB][NI];
__device__ int   g_sel[BB][NI][EE];
__device__ __align__(16) __nv_bfloat16 g_ebh[BB][NPTS][CC];  // point-major bf16
__device__ float g_sq[BB][NPTS];
__device__ float g_var_raw;
__device__ float g_dist_raw;
__device__ float g_edge_raw;
__device__ float g_reg_raw;

// ---------------------------------------------------------------- zero scratch
__global__ void k_zero() {
    int i = blockIdx.x * blockDim.x + threadIdx.x;
    int stride = gridDim.x * blockDim.x;
    float* sums = &g_sums[0][0][0];
    for (int k = i; k < BB*NI*CC; k += stride) sums[k] = 0.0f;
    if (i < BB*NI) (&g_counts[0][0])[i] = 0.0f;
    int* sel = &g_sel[0][0][0];
    for (int k = i; k < BB*NI*EE; k += stride) sel[k] = 0;
    if (i == 0) { g_var_raw = 0.0f; g_dist_raw = 0.0f; g_edge_raw = 0.0f; g_reg_raw = 0.0f; }
}

// ------------------------------------------------- pass A: label sums + counts
// 1024 blocks (BB*256), 256 threads. Labels staged in smem once. Warp w owns
// channels [4w,4w+4); lane handles 4 consecutive pixels via float4 per iter.
// Accumulation = mask(0/1) FFMA into register acc[8][4].
#define NCHUNK_S 256
#define CHPX_S 1024

__global__ __launch_bounds__(256) void k_stats(const float* __restrict__ feat,
                                               const int* __restrict__ labels) {
    int b = blockIdx.x >> 8;
    int chunk = blockIdx.x & 255;
    int base = chunk * CHPX_S;
    const float* f = feat + (size_t)b * CC * PP;
    const int* lb = labels + (size_t)b * PP;

    int t = threadIdx.x;
    __shared__ int slab[CHPX_S];
    *(int4*)&slab[t * 4] = *(const int4*)&lb[base + t * 4];
    __syncthreads();

    int w = t >> 5, lane = t & 31;
    int c0 = w * 4;

    float acc[NI][4];
#pragma unroll
    for (int n = 0; n < NI; n++)
#pragma unroll
        for (int e = 0; e < 4; e++) acc[n][e] = 0.0f;

#pragma unroll
    for (int it = 0; it < 8; it++) {
        int pofs = it * 128 + lane * 4;
        const float* fp = f + base + pofs;
        float4 va = *(const float4*)&fp[(size_t)(c0 + 0) * PP];
        float4 vb = *(const float4*)&fp[(size_t)(c0 + 1) * PP];
        float4 vc = *(const float4*)&fp[(size_t)(c0 + 2) * PP];
        float4 vd = *(const float4*)&fp[(size_t)(c0 + 3) * PP];
        int l[4] = { slab[pofs], slab[pofs + 1], slab[pofs + 2], slab[pofs + 3] };
        float vj[4][4] = { {va.x, vb.x, vc.x, vd.x},
                           {va.y, vb.y, vc.y, vd.y},
                           {va.z, vb.z, vc.z, vd.z},
                           {va.w, vb.w, vc.w, vd.w} };
#pragma unroll
        for (int j = 0; j < 4; j++) {
#pragma unroll
            for (int n = 0; n < NI; n++) {
                float m = (l[j] == n) ? 1.0f : 0.0f;
                acc[n][0] = fmaf(m, vj[j][0], acc[n][0]);
                acc[n][1] = fmaf(m, vj[j][1], acc[n][1]);
                acc[n][2] = fmaf(m, vj[j][2], acc[n][2]);
                acc[n][3] = fmaf(m, vj[j][3], acc[n][3]);
            }
        }
    }

#pragma unroll
    for (int n = 0; n < NI; n++)
#pragma unroll
        for (int e = 0; e < 4; e++) {
            float a = acc[n][e];
#pragma unroll
            for (int o = 16; o > 0; o >>= 1) a += __shfl_xor_sync(0xffffffffu, a, o);
            acc[n][e] = a;
        }
    if (lane == 0) {
#pragma unroll
        for (int n = 0; n < NI; n++)
#pragma unroll
            for (int e = 0; e < 4; e++)
                atomicAdd(&g_sums[b][n][c0 + e], acc[n][e]);
    }

    // counts: warp 0 only, one sweep of smem labels
    if (w == 0) {
        int cnt[NI];
#pragma unroll
        for (int n = 0; n < NI; n++) cnt[n] = 0;
        for (int i = lane; i < CHPX_S; i += 32) {
            int l = slab[i];
#pragma unroll
            for (int n = 0; n < NI; n++) cnt[n] += (l == n);
        }
#pragma unroll
        for (int n = 0; n < NI; n++) {
            int a = cnt[n];
#pragma unroll
            for (int o = 16; o > 0; o >>= 1) a += __shfl_xor_sync(0xffffffffu, a, o);
            cnt[n] = a;
        }
        if (lane == 0) {
#pragma unroll
            for (int n = 0; n < NI; n++)
                atomicAdd(&g_counts[b][n], (float)cnt[n]);
        }
    }
}

// ----------------------------------- means + inv counts + dist loss + reg loss
__global__ void k_means() {
    int b = blockIdx.x;
    int t = threadIdx.x;          // 256
    int n = t >> 5, c = t & 31;
    float cntv = g_counts[b][n];
    float mean = g_sums[b][n][c] / cntv;
    g_means[b][n][c] = mean;
    if (c == 0) g_invc[b][n] = 1.0f / cntv;
    __shared__ float sm[NI][CC];
    __shared__ float sM2[NI];
    sm[n][c] = mean;
    float m2 = mean * mean;
#pragma unroll
    for (int o = 16; o > 0; o >>= 1) m2 += __shfl_xor_sync(0xffffffffu, m2, o);
    if (c == 0) sM2[n] = m2;
    __syncthreads();
    if (t == 0) {
        float r = 0.0f;
#pragma unroll
        for (int nn = 0; nn < NI; nn++)
            r += sqrtf(fmaxf(sM2[nn], 0.0f) + 1e-12f);
        atomicAdd(&g_reg_raw, r * (1.0f / (float)NI));
    }
    if (t < NPAIRS) {
        int i = 0, rem = t;
        while (rem >= (NI - 1) - i) { rem -= (NI - 1) - i; i++; }
        int j = i + 1 + rem;
        float d2 = 0.0f;
#pragma unroll
        for (int cc2 = 0; cc2 < CC; cc2++) {
            float df = sm[i][cc2] - sm[j][cc2];
            d2 += df * df;
        }
        float dm = sqrtf(fmaxf(d2, 0.0f) + 1e-12f);
        float h = fmaxf(3.0f - dm, 0.0f);   // 2*DD - dm
        atomicAdd(&g_dist_raw, h * h);
    }
}

// ------------------------------------------------ pass B: variance (pull) loss
// 1024 blocks (BB*256), 256 threads, 4 px/thread. invcount folded into hinge
// so only a single scalar is reduced per block.
#define NCHUNK_V 256
#define CHPX_V 1024

__global__ __launch_bounds__(256) void k_var(const float* __restrict__ feat,
                                             const int* __restrict__ labels) {
    int b = blockIdx.x >> 8;
    int chunk = blockIdx.x & 255;
    int base = chunk * CHPX_V;
    const float* f = feat + (size_t)b * CC * PP;
    const int* lb = labels + (size_t)b * PP;
    int t = threadIdx.x;

    __shared__ float sm[NI * 36];
    __shared__ float sinv[NI];
    __shared__ float wred[8];
    { int n = t >> 5, c = t & 31; sm[n * 36 + c] = g_means[b][n][c]; }
    if (t < NI) sinv[t] = g_invc[b][t];
    __syncthreads();

    int p4 = base + t * 4;
    int4 L = *(const int4*)&lb[p4];
    int lv[4] = { L.x, L.y, L.z, L.w };

    float d2[4] = { 0.0f, 0.0f, 0.0f, 0.0f };
#pragma unroll
    for (int cg = 0; cg < 8; cg++) {
        float4 v0 = *(const float4*)&f[(size_t)(cg * 4 + 0) * PP + p4];
        float4 v1 = *(const float4*)&f[(size_t)(cg * 4 + 1) * PP + p4];
        float4 v2 = *(const float4*)&f[(size_t)(cg * 4 + 2) * PP + p4];
        float4 v3 = *(const float4*)&f[(size_t)(cg * 4 + 3) * PP + p4];
        float vj[4][4] = { {v0.x, v1.x, v2.x, v3.x},
                           {v0.y, v1.y, v2.y, v3.y},
                           {v0.z, v1.z, v2.z, v3.z},
                           {v0.w, v1.w, v2.w, v3.w} };
#pragma unroll
        for (int j = 0; j < 4; j++) {
            float4 m = *(const float4*)&sm[lv[j] * 36 + cg * 4];
            float t0 = vj[j][0] - m.x;
            float t1 = vj[j][1] - m.y;
            float t2 = vj[j][2] - m.z;
            float t3 = vj[j][3] - m.w;
            d2[j] += t0 * t0 + t1 * t1 + t2 * t2 + t3 * t3;
        }
    }

    float hsum = 0.0f;
#pragma unroll
    for (int j = 0; j < 4; j++) {
        float d = sqrtf(d2[j] + 1e-12f);
        float h = fmaxf(d - 0.5f, 0.0f);          // DV = 0.5
        hsum += h * h * sinv[lv[j]];
    }
#pragma unroll
    for (int o = 16; o > 0; o >>= 1) hsum += __shfl_xor_sync(0xffffffffu, hsum, o);
    if ((t & 31) == 0) wred[t >> 5] = hsum;
    __syncthreads();
    if (t == 0) {
        float s = 0.0f;
#pragma unroll
        for (int w2 = 0; w2 < 8; w2++) s += wred[w2];
        atomicAdd(&g_var_raw, s);
    }
}

// ------------------------- edge selection: first EE pixels (ascending index)
// One block per (b, instance); shfl-based hierarchical scan replaces the
// 10-round serial shared scan.
__global__ __launch_bounds__(1024) void k_select(const int* __restrict__ labelEdges) {
    int b = blockIdx.x >> 3;
    int inst = blockIdx.x & 7;
    const int* le = labelEdges + (size_t)b * PP;
    int t = threadIdx.x;                 // 1024 threads
    const int PT = PP / 1024;            // 256 pixels per thread
    int start = t * PT;

    int cnt = 0;
    for (int k = 0; k < PT / 4; k++) {
        int4 q = *(const int4*)&le[start + k * 4];
        cnt += (q.x == inst) + (q.y == inst) + (q.z == inst) + (q.w == inst);
    }
    int lane = t & 31, wid = t >> 5;
    int v = cnt;
#pragma unroll
    for (int off = 1; off < 32; off <<= 1) {
        int u = __shfl_up_sync(0xffffffffu, v, off);
        if (lane >= off) v += u;
    }
    __shared__ int wsum[32];
    if (lane == 31) wsum[wid] = v;
    __syncthreads();
    if (wid == 0) {
        int x = wsum[lane];
#pragma unroll
        for (int off = 1; off < 32; off <<= 1) {
            int u = __shfl_up_sync(0xffffffffu, x, off);
            if (lane >= off) x += u;
        }
        wsum[lane] = x;
    }
    __syncthreads();
    int rank = (wid ? wsum[wid - 1] : 0) + v - cnt;   // exclusive global prefix
    if (rank < EE && cnt > 0) {
        for (int k = 0; k < PT / 4; k++) {
            int4 q = *(const int4*)&le[start + k * 4];
            int p = start + k * 4;
            if (q.x == inst) { if (rank < EE) g_sel[b][inst][rank] = p;     rank++; }
            if (q.y == inst) { if (rank < EE) g_sel[b][inst][rank] = p + 1; rank++; }
            if (q.z == inst) { if (rank < EE) g_sel[b][inst][rank] = p + 2; rank++; }
            if (q.w == inst) { if (rank < EE) g_sel[b][inst][rank] = p + 3; rank++; }
            if (rank >= EE) break;
        }
    }
}

// ------------------ gather edge features -> bf16 point-major + squared norms
// 256 blocks x 256 threads: thread = (point, 8-channel group); 4 lanes share a
// point and shfl-combine the squared norm.
__global__ __launch_bounds__(256) void k_gather(const float* __restrict__ feat) {
    int gidx = blockIdx.x * 256 + threadIdx.x;
    int b = gidx >> 14;                 // 16384 threads per image
    int r = gidx & 16383;
    int pt = r >> 2;
    int cg = r & 3;
    int inst = pt >> 9;
    int e = pt & (EE - 1);
    int idx = g_sel[b][inst][e];
    const float* f = feat + (size_t)b * CC * PP;

    float sq = 0.0f;
    unsigned pk[4];
#pragma unroll
    for (int k = 0; k < 4; k++) {
        float va = f[(size_t)(cg * 8 + 2 * k) * PP + idx];
        float vb = f[(size_t)(cg * 8 + 2 * k + 1) * PP + idx];
        sq += va * va + vb * vb;
        __nv_bfloat162 h = __floats2bfloat162_rn(va, vb);
        pk[k] = *reinterpret_cast<unsigned*>(&h);
    }
    *(uint4*)&g_ebh[b][pt][cg * 8] = make_uint4(pk[0], pk[1], pk[2], pk[3]);

    sq += __shfl_xor_sync(0xffffffffu, sq, 1);
    sq += __shfl_xor_sync(0xffffffffu, sq, 2);
    if (cg == 0) g_sq[b][pt] = sq;      // sq in fp32 from original floats
}

// ----------------------- edge pair loss via bf16 mma.sync (m16n8k16)
// Block tile 64(i) x 128(j), 8 warps in 4x2 layout, warp tile 16x64.
// d2 = sqA + sqB - 2*dot; hinge active only when d2 < 4 (essentially never).
__global__ __launch_bounds__(256) void k_pairs() {
    int b = blockIdx.y;
    int x = blockIdx.x;
    int pair = x >> 5;
    int tile = x & 31;
    int i = 0, rem = pair;
    while (rem >= (NI - 1) - i) { rem -= (NI - 1) - i; i++; }
    int j = i + 1 + rem;
    int ti = tile >> 2, tj = tile & 3;
    int i0 = i * EE + ti * 64;
    int j0 = j * EE + tj * 128;

    __shared__ __align__(16) __nv_bfloat16 As[64][40];    // pad: 80B rows
    __shared__ __align__(16) __nv_bfloat16 Bs[128][40];
    __shared__ float sqa[64], sqb[128];
    __shared__ float wred[8];

    int t = threadIdx.x;
    {
        int row = t >> 2, ch = t & 3;
        *(uint4*)&As[row][ch * 8]      = *(const uint4*)&g_ebh[b][i0 + row][ch * 8];
        *(uint4*)&Bs[row][ch * 8]      = *(const uint4*)&g_ebh[b][j0 + row][ch * 8];
        *(uint4*)&Bs[row + 64][ch * 8] = *(const uint4*)&g_ebh[b][j0 + row + 64][ch * 8];
    }
    if (t < 64) sqa[t] = g_sq[b][i0 + t];
    else if (t < 192) sqb[t - 64] = g_sq[b][j0 + (t - 64)];
    __syncthreads();

    int w = t >> 5, lane = t & 31;
    int wi = w >> 1, wj = w & 1;
    int r0 = wi * 16, cb0 = wj * 64;
    int g = lane >> 2, tq = lane & 3;

    unsigned a[2][4];
#pragma unroll
    for (int ks = 0; ks < 2; ks++) {
        int kb = ks * 16 + 2 * tq;
        a[ks][0] = *(const unsigned*)&As[r0 + g][kb];
        a[ks][1] = *(const unsigned*)&As[r0 + g + 8][kb];
        a[ks][2] = *(const unsigned*)&As[r0 + g][kb + 8];
        a[ks][3] = *(const unsigned*)&As[r0 + g + 8][kb + 8];
    }
    float sa0 = sqa[r0 + g], sa1 = sqa[r0 + g + 8];
    float acc = 0.0f;

#pragma unroll
    for (int nt = 0; nt < 8; nt++) {
        int cb = cb0 + nt * 8;
        unsigned b00 = *(const unsigned*)&Bs[cb + g][2 * tq];
        unsigned b01 = *(const unsigned*)&Bs[cb + g][2 * tq + 8];
        unsigned b10 = *(const unsigned*)&Bs[cb + g][16 + 2 * tq];
        unsigned b11 = *(const unsigned*)&Bs[cb + g][16 + 2 * tq + 8];
        float d0 = 0.0f, d1 = 0.0f, d2v = 0.0f, d3 = 0.0f;
        asm volatile(
            "mma.sync.aligned.m16n8k16.row.col.f32.bf16.bf16.f32 "
            "{%0,%1,%2,%3}, {%4,%5,%6,%7}, {%8,%9}, {%0,%1,%2,%3};"
            : "+f"(d0), "+f"(d1), "+f"(d2v), "+f"(d3)
            : "r"(a[0][0]), "r"(a[0][1]), "r"(a[0][2]), "r"(a[0][3]),
              "r"(b00), "r"(b01));
        asm volatile(
            "mma.sync.aligned.m16n8k16.row.col.f32.bf16.bf16.f32 "
            "{%0,%1,%2,%3}, {%4,%5,%6,%7}, {%8,%9}, {%0,%1,%2,%3};"
            : "+f"(d0), "+f"(d1), "+f"(d2v), "+f"(d3)
            : "r"(a[1][0]), "r"(a[1][1]), "r"(a[1][2]), "r"(a[1][3]),
              "r"(b10), "r"(b11));

        float sb0 = sqb[cb + 2 * tq], sb1 = sqb[cb + 2 * tq + 1];
        float q00 = sa0 + sb0 - 2.0f * d0;
        float q01 = sa0 + sb1 - 2.0f * d1;
        float q10 = sa1 + sb0 - 2.0f * d2v;
        float q11 = sa1 + sb1 - 2.0f * d3;
        if (q00 < 4.0f) { float h = fmaxf(2.0f - sqrtf(fmaxf(q00, 0.0f) + 1e-12f), 0.0f); acc += h * h; }
        if (q01 < 4.0f) { float h = fmaxf(2.0f - sqrtf(fmaxf(q01, 0.0f) + 1e-12f), 0.0f); acc += h * h; }
        if (q10 < 4.0f) { float h = fmaxf(2.0f - sqrtf(fmaxf(q10, 0.0f) + 1e-12f), 0.0f); acc += h * h; }
        if (q11 < 4.0f) { float h = fmaxf(2.0f - sqrtf(fmaxf(q11, 0.0f) + 1e-12f), 0.0f); acc += h * h; }
    }

#pragma unroll
    for (int o = 16; o > 0; o >>= 1) acc += __shfl_xor_sync(0xffffffffu, acc, o);
    if (lane == 0) wred[w] = acc;
    __syncthreads();
    if (t == 0) {
        float s = 0.0f;
#pragma unroll
        for (int w2 = 0; w2 < 8; w2++) s += wred[w2];
        if (s != 0.0f) atomicAdd(&g_edge_raw, s);
    }
}

// --------------------------------------------------------------- finalize
__global__ void k_final(float* __restrict__ out) {
    float var  = g_var_raw * (1.0f / (float)NI);                      // ALPHA = 1
    float dist = g_dist_raw * (1.0f / 56.0f);                          // BETA = 1
    float edge = g_edge_raw * (1.0f / (512.0f * 512.0f * 56.0f));      // GAMMA = 1
    float reg  = 0.001f * g_reg_raw;                                   // DELTA
    out[0] = var + dist + edge + reg;
    out[1] = var;
    out[2] = dist;
    out[3] = edge;
    out[4] = reg;
}

// ------------------------------------------------------------------ launcher
extern "C" void kernel_launch(void* const* d_in, const int* in_sizes, int n_in,
                              void* d_out, int out_size) {
    const float* features   = (const float*)d_in[0];
    const int*   labels     = (const int*)d_in[1];
    const int*   labelEdges = (const int*)d_in[2];
    float* out = (float*)d_out;
    (void)in_sizes; (void)n_in; (void)out_size;

    k_zero<<<32, 256>>>();
    k_stats<<<BB * NCHUNK_S, 256>>>(features, labels);
    k_means<<<BB, 256>>>();
    k_var<<<BB * NCHUNK_V, 256>>>(features, labels);
    k_select<<<BB * NI, 1024>>>(labelEdges);
    k_gather<<<256, 256>>>(features);
    k_pairs<<<dim3(NPAIRS * 32, BB), 256>>>();
    k_final<<<1, 1>>>(out);
}